// round 9
// baseline (speedup 1.0000x reference)
#include <cuda_runtime.h>

#define NUM_FACES 13776
#define MAXC 8
#define EPSF 1e-8f
#define GRID 148
#define TPB 1024
#define NWARPS (GRID * (TPB / 32))   // 4736
#define NCOLS0 128                   // fast-path scan depth (4 chunks of 32)
#define SEG_COLS 1024                // straggler segment width
#define NSEG 14                      // ceil((13776-128)/1024)

// ---- device scratch (static; no runtime allocations) ----
__device__ float4 g_bbmin[NUM_FACES];     // (minx,miny,minz, face_id0 bits)
__device__ float4 g_bbmax[NUM_FACES];     // (maxx,maxy,maxz, face_id1 bits)
__device__ int    g_f2[NUM_FACES];        // face_id2
__device__ float  g_tri[NUM_FACES * 12];  // 9 floats per face, padded to 48B
__device__ int    g_cnt[NUM_FACES];       // pairs found in first 128 cols (<=8)
__device__ int    g_pairs[NUM_FACES * MAXC];
__device__ int    g_strag[NUM_FACES];     // straggler worklist (rows, cnt<8)
__device__ int    g_ns;                   // worklist size
__device__ int    g_seg_cnt[NUM_FACES];   // per (straggler,seg) item found count
__device__ int    g_seg_js[NUM_FACES * MAXC];  // per item first <=8 column ids
__device__ double g_accum;
__device__ unsigned g_bar_count;
__device__ volatile unsigned g_bar_sense;
__device__ unsigned g_done;

// NOTE: g_seg_cnt/g_seg_js are indexed by item = w*NSEG + s with w < ns.
// ns*NSEG <= NUM_FACES requires ns <= 984; empirically ns is O(10-100).
// Hard safety: items beyond capacity are skipped (rows then use partial
// pairs only; never out-of-bounds).
#define MAX_ITEMS NUM_FACES

// Sense-reversing grid barrier. Safe: 148 blocks x 1024 thr at 1 block/SM ->
// wave-1 placement keeps every block resident while spinning. Self-resetting.
__device__ __forceinline__ void grid_barrier() {
    __threadfence();
    __syncthreads();
    if (threadIdx.x == 0) {
        unsigned s = g_bar_sense;
        unsigned old = atomicAdd(&g_bar_count, 1u);
        if (old == GRID - 1) {
            g_bar_count = 0;
            __threadfence();
            g_bar_sense = s ^ 1u;
        } else {
            while (g_bar_sense == s) { __nanosleep(32); }
        }
        __threadfence();
    }
    __syncthreads();
}

struct Tri { float3 v0, v1, v2; };

__device__ __forceinline__ Tri load_tri(int f) {
    const float4* p = (const float4*)&g_tri[f * 12];
    float4 q0 = p[0], q1 = p[1], q2 = p[2];
    Tri t;
    t.v0 = make_float3(q0.x, q0.y, q0.z);
    t.v1 = make_float3(q0.w, q1.x, q1.y);
    t.v2 = make_float3(q1.z, q1.w, q2.x);
    return t;
}

// Cone-field penalty of src triangle A at the 3 verts of P. SIGMA=0.5 -> *2.
__device__ __forceinline__ float cone_pen(const Tri& A, const Tri& P) {
    float e0x = A.v1.x - A.v0.x, e0y = A.v1.y - A.v0.y, e0z = A.v1.z - A.v0.z;
    float e1x = A.v2.x - A.v0.x, e1y = A.v2.y - A.v0.y, e1z = A.v2.z - A.v0.z;

    float nx = e0y * e1z - e0z * e1y;
    float ny = e0z * e1x - e0x * e1z;
    float nz = e0x * e1y - e0y * e1x;
    float nn = sqrtf(nx * nx + ny * ny + nz * nz);
    float inv = 1.0f / (nn + EPSF);
    nx *= inv; ny *= inv; nz *= inv;

    float cx = (A.v0.x + A.v1.x + A.v2.x) * (1.0f / 3.0f);
    float cy = (A.v0.y + A.v1.y + A.v2.y) * (1.0f / 3.0f);
    float cz = (A.v0.z + A.v1.z + A.v2.z) * (1.0f / 3.0f);

    const float3* pv = &P.v0;
    float pen = 0.0f;
#pragma unroll
    for (int v = 0; v < 3; v++) {
        float ux = pv[v].x - cx;
        float uy = pv[v].y - cy;
        float uz = pv[v].z - cz;
        float h = ux * nx + uy * ny + uz * nz;
        float wx = ux - h * nx;
        float wy = uy - h * ny;
        float wz = uz - h * nz;
        float r = sqrtf(wx * wx + wy * wy + wz * wz);
        float radial = fmaxf(1.0f - r * 2.0f, 0.0f);
        float depth = fmaxf(-h, 0.0f) + fmaxf(h, 0.0f) * __expf(-h * 2.0f);
        float phi = radial * depth;
        pen += phi * phi;
    }
    return pen;
}

__device__ __forceinline__ bool pair_ok(const float4& bmin, const float4& bmax,
                                        int rf0, int rf1, int rf2,
                                        const float4& jmin, const float4& jmax,
                                        int jf2) {
    bool ok = (bmin.x <= jmax.x) && (jmin.x <= bmax.x) &&
              (bmin.y <= jmax.y) && (jmin.y <= bmax.y) &&
              (bmin.z <= jmax.z) && (jmin.z <= bmax.z);
    if (ok) {
        int jf0 = __float_as_int(jmin.w);
        int jf1 = __float_as_int(jmax.w);
        bool share = (rf0 == jf0) | (rf0 == jf1) | (rf0 == jf2) |
                     (rf1 == jf0) | (rf1 == jf1) | (rf1 == jf2) |
                     (rf2 == jf0) | (rf2 == jf1) | (rf2 == jf2);
        ok = !share;
    }
    return ok;
}

// ---------------------------------------------------------------------------
// ONE persistent kernel:
//   setup | bar | 2a: warp-per-row (128 cols, no branch) | bar |
//   2b: WARP-per-(row,segment) items + thread-per-pair narrow phase | bar |
//   merge+eval stragglers | epilogue
// The worst row's deep scan is parallelized across its 14 segment items.
// ---------------------------------------------------------------------------
__global__ void __launch_bounds__(TPB, 1)
fused_kernel(const float* __restrict__ verts,
             const int*   __restrict__ faces,
             float*       __restrict__ out) {
    __shared__ double s_bsum;
    __shared__ int    s_sj[32][MAXC];
    __shared__ int    s_sm[32];

    int tid = threadIdx.x;
    int lane = tid & 31;
    int wwid = tid >> 5;
    int gwarp = (int)blockIdx.x * 32 + wwid;
    unsigned below = (1u << lane) - 1u;

    if (tid == 0) s_bsum = 0.0;
    if (blockIdx.x == 0 && tid == 0) g_ns = 0;

    // ---------- Phase 1: setup, 4 lanes per face ---------------------------
    {
        int group = tid >> 2;
        int l = tid & 3;
        int f = group * GRID + (int)blockIdx.x;
        int fc = (f < NUM_FACES) ? f : (NUM_FACES - 1);
        int comp = (l < 2) ? l : 2;
        int idx = faces[3 * fc + comp];
        float x = verts[3 * idx + 0];
        float y = verts[3 * idx + 1];
        float z = verts[3 * idx + 2];

        if (f < NUM_FACES && l < 3) {
            g_tri[f * 12 + 3 * l + 0] = x;
            g_tri[f * 12 + 3 * l + 1] = y;
            g_tri[f * 12 + 3 * l + 2] = z;
        }

        float mnx = x, mny = y, mnz = z, mxx = x, mxy = y, mxz = z;
#pragma unroll
        for (int off = 1; off <= 2; off <<= 1) {
            mnx = fminf(mnx, __shfl_xor_sync(0xffffffffu, mnx, off));
            mny = fminf(mny, __shfl_xor_sync(0xffffffffu, mny, off));
            mnz = fminf(mnz, __shfl_xor_sync(0xffffffffu, mnz, off));
            mxx = fmaxf(mxx, __shfl_xor_sync(0xffffffffu, mxx, off));
            mxy = fmaxf(mxy, __shfl_xor_sync(0xffffffffu, mxy, off));
            mxz = fmaxf(mxz, __shfl_xor_sync(0xffffffffu, mxz, off));
        }
        int i1 = __shfl_xor_sync(0xffffffffu, idx, 1);
        int i2 = __shfl_xor_sync(0xffffffffu, idx, 2);

        if (f < NUM_FACES && l == 0) {
            g_bbmin[f] = make_float4(mnx, mny, mnz, __int_as_float(idx));
            g_bbmax[f] = make_float4(mxx, mxy, mxz, __int_as_float(i1));
            g_f2[f]    = i2;
        }
    }

    grid_barrier();   // AABBs + triangles + g_ns reset visible

    // ---------- Phase 2a: warp-per-row, exactly 128 columns, branch-free ---
    for (int row = gwarp; row < NUM_FACES; row += NWARPS) {
        float4 bmin = g_bbmin[row];
        float4 bmax = g_bbmax[row];
        int rf0 = __float_as_int(bmin.w);
        int rf1 = __float_as_int(bmax.w);
        int rf2 = g_f2[row];

        int found = 0;
#pragma unroll
        for (int c = 0; c < NCOLS0 / 32; c++) {
            int j = (c << 5) + lane;
            float4 jmin = g_bbmin[j];
            float4 jmax = g_bbmax[j];
            bool ok = pair_ok(bmin, bmax, rf0, rf1, rf2, jmin, jmax, g_f2[j]);
            unsigned m = __ballot_sync(0xffffffffu, ok);
            int rank = found + __popc(m & below);
            if (ok && rank < MAXC) g_pairs[(row << 3) + rank] = j;
            found += __popc(m);
        }
        int cnt = min(found, MAXC);
        if (lane == 0) {
            g_cnt[row] = cnt;
            if (cnt < MAXC) {
                int w = atomicAdd(&g_ns, 1);
                g_strag[w] = row;
            }
        }
    }

    grid_barrier();   // partial pair lists + worklist visible

    // ---------- Phase 2b-i: straggler segment items, warp-per-item ---------
    {
        int nitems = min(g_ns * NSEG, MAX_ITEMS);
        for (int item = gwarp; item < nitems; item += NWARPS) {
            int w = item / NSEG;
            int s = item - w * NSEG;
            int row = g_strag[w];
            int need = MAXC - g_cnt[row];      // >= 1

            float4 bmin = g_bbmin[row];
            float4 bmax = g_bbmax[row];
            int rf0 = __float_as_int(bmin.w);
            int rf1 = __float_as_int(bmax.w);
            int rf2 = g_f2[row];

            int start = NCOLS0 + s * SEG_COLS;
            int end = min(start + SEG_COLS, NUM_FACES);
            int found = 0;
            for (int base = start; base < end; base += 128) {  // 4-chunk strip
#pragma unroll
                for (int u = 0; u < 4; u++) {
                    int j = base + (u << 5) + lane;
                    bool ok = false;
                    if (j < end) {
                        float4 jmin = g_bbmin[j];
                        float4 jmax = g_bbmax[j];
                        ok = pair_ok(bmin, bmax, rf0, rf1, rf2, jmin, jmax,
                                     g_f2[j]);
                    }
                    unsigned m = __ballot_sync(0xffffffffu, ok);
                    int rank = found + __popc(m & below);
                    if (ok && rank < MAXC) g_seg_js[(item << 3) + rank] = j;
                    found += __popc(m);
                }
                if (found >= need) break;      // enough for this row
            }
            if (lane == 0) g_seg_cnt[item] = min(found, MAXC);
        }
    }

    // ---------- Phase 2b-ii: narrow phase for all pairs found in 2a --------
    // (straggler rows' partial pairs are final prefix entries: safe to eval)
    {
        int t = (int)blockIdx.x * TPB + tid;   // 151552 >= 110208 slots
        float pen = 0.0f;
        if (t < NUM_FACES * MAXC) {
            int row = t >> 3;
            int k = t & 7;
            if (k < g_cnt[row]) {
                int j = g_pairs[t];
                Tri R = load_tri(row);
                Tri J = load_tri(j);
                pen = cone_pen(R, J) + cone_pen(J, R);
            }
        }
#pragma unroll
        for (int off = 16; off > 0; off >>= 1)
            pen += __shfl_xor_sync(0xffffffffu, pen, off);
        if (lane == 0 && pen != 0.0f) atomicAdd(&s_bsum, (double)pen);
    }

    grid_barrier();   // all segment results visible

    // ---------- Phase 3: merge + eval straggler appends, warp-per-row ------
    {
        int ns = g_ns;
        int nitems_cap = min(ns * NSEG, MAX_ITEMS) / NSEG;  // rows with slots
        for (int w = gwarp; w < ns; w += NWARPS) {
            int row = g_strag[w];
            int need = MAXC - g_cnt[row];
            int m = 0;
            if (lane == 0) {
                if (w < nitems_cap) {
                    for (int s = 0; s < NSEG && m < need; s++) {
                        int item = w * NSEG + s;
                        int c = g_seg_cnt[item];
                        for (int k = 0; k < c && m < need; k++)
                            s_sj[wwid][m++] = g_seg_js[(item << 3) + k];
                    }
                }
                s_sm[wwid] = m;
            }
            __syncwarp();
            m = s_sm[wwid];

            float pen = 0.0f;
            int pairIdx = lane >> 1;
            int dir = lane & 1;
            if (lane < 16 && pairIdx < m) {
                int j = s_sj[wwid][pairIdx];
                Tri R = load_tri(row);
                Tri J = load_tri(j);
                pen = dir ? cone_pen(J, R) : cone_pen(R, J);
            }
#pragma unroll
            for (int off = 16; off > 0; off >>= 1)
                pen += __shfl_xor_sync(0xffffffffu, pen, off);
            if (lane == 0 && pen != 0.0f) atomicAdd(&s_bsum, (double)pen);
            __syncwarp();
        }
    }
    __syncthreads();

    // ---------- Epilogue: last block writes output, resets state -----------
    if (tid == 0) {
        if (s_bsum != 0.0) atomicAdd(&g_accum, s_bsum);
        __threadfence();
        unsigned old = atomicAdd(&g_done, 1u);
        if (old == GRID - 1) {
            g_done = 0;
            unsigned long long bits =
                atomicExch((unsigned long long*)&g_accum, 0ULL);
            out[0] = (float)__longlong_as_double(bits);   // weight = 1.0
        }
    }
}

extern "C" void kernel_launch(void* const* d_in, const int* in_sizes, int n_in,
                              void* d_out, int out_size) {
    const float* verts = (const float*)d_in[0];
    const int*   faces = (const int*)d_in[1];
    float*       out   = (float*)d_out;

    fused_kernel<<<GRID, TPB>>>(verts, faces, out);
}

// round 10
// speedup vs baseline: 1.2120x; 1.2120x over previous
#include <cuda_runtime.h>

#define NUM_FACES 13776
#define MAXC 8
#define EPSF 1e-8f

// ---- device scratch (static; no runtime allocations) ----
// g_bb0[f] = (minx,miny,minz, bits(i0 | i1<<16))   ids < 6890 < 2^16
// g_bb1[f] = (maxx,maxy,maxz, bits(i2))
__device__ float4 g_bb0[NUM_FACES];
__device__ float4 g_bb1[NUM_FACES];
__device__ double g_accum;        // self-resetting
__device__ unsigned g_done;       // self-resetting

#define K2_BLOCKS (NUM_FACES / 8) // 1722 blocks, 8 warps each, warp-per-row

// ---------------------------------------------------------------------------
// Kernel 1: thread-per-face AABB + packed face ids. No triangle staging.
// ---------------------------------------------------------------------------
__global__ void __launch_bounds__(128) setup_kernel(
        const float* __restrict__ verts, const int* __restrict__ faces) {
    int f = blockIdx.x * blockDim.x + threadIdx.x;
    if (f >= NUM_FACES) return;

    int i0 = faces[3 * f + 0];
    int i1 = faces[3 * f + 1];
    int i2 = faces[3 * f + 2];

    float x0 = verts[3 * i0], y0 = verts[3 * i0 + 1], z0 = verts[3 * i0 + 2];
    float x1 = verts[3 * i1], y1 = verts[3 * i1 + 1], z1 = verts[3 * i1 + 2];
    float x2 = verts[3 * i2], y2 = verts[3 * i2 + 1], z2 = verts[3 * i2 + 2];

    float mnx = fminf(x0, fminf(x1, x2));
    float mny = fminf(y0, fminf(y1, y2));
    float mnz = fminf(z0, fminf(z1, z2));
    float mxx = fmaxf(x0, fmaxf(x1, x2));
    float mxy = fmaxf(y0, fmaxf(y1, y2));
    float mxz = fmaxf(z0, fmaxf(z1, z2));

    g_bb0[f] = make_float4(mnx, mny, mnz, __int_as_float(i0 | (i1 << 16)));
    g_bb1[f] = make_float4(mxx, mxy, mxz, __int_as_float(i2));
}

struct Tri { float3 v0, v1, v2; };

__device__ __forceinline__ float3 vert3(const float* __restrict__ v, int i) {
    return make_float3(v[3 * i], v[3 * i + 1], v[3 * i + 2]);
}

// Cone-field penalty of src triangle A at the 3 verts of P. SIGMA=0.5 -> *2.
__device__ __forceinline__ float cone_pen(const Tri& A, const Tri& P) {
    float e0x = A.v1.x - A.v0.x, e0y = A.v1.y - A.v0.y, e0z = A.v1.z - A.v0.z;
    float e1x = A.v2.x - A.v0.x, e1y = A.v2.y - A.v0.y, e1z = A.v2.z - A.v0.z;

    float nx = e0y * e1z - e0z * e1y;
    float ny = e0z * e1x - e0x * e1z;
    float nz = e0x * e1y - e0y * e1x;
    float nn = sqrtf(nx * nx + ny * ny + nz * nz);
    float inv = 1.0f / (nn + EPSF);
    nx *= inv; ny *= inv; nz *= inv;

    float cx = (A.v0.x + A.v1.x + A.v2.x) * (1.0f / 3.0f);
    float cy = (A.v0.y + A.v1.y + A.v2.y) * (1.0f / 3.0f);
    float cz = (A.v0.z + A.v1.z + A.v2.z) * (1.0f / 3.0f);

    const float3* pv = &P.v0;
    float pen = 0.0f;
#pragma unroll
    for (int v = 0; v < 3; v++) {
        float ux = pv[v].x - cx;
        float uy = pv[v].y - cy;
        float uz = pv[v].z - cz;
        float h = ux * nx + uy * ny + uz * nz;
        float wx = ux - h * nx;
        float wy = uy - h * ny;
        float wz = uz - h * nz;
        float r = sqrtf(wx * wx + wy * wy + wz * wz);
        float radial = fmaxf(1.0f - r * 2.0f, 0.0f);
        float depth = fmaxf(-h, 0.0f) + fmaxf(h, 0.0f) * __expf(-h * 2.0f);
        float phi = radial * depth;
        pen += phi * phi;
    }
    return pen;
}

// ---------------------------------------------------------------------------
// Kernel 2: warp-per-row serial ballot scan (first 8 ascending == stable
// top_k), immediate 16-lane narrow eval, block reduce, fused finalize.
// ---------------------------------------------------------------------------
__global__ void __launch_bounds__(256) collide_kernel(
        const float* __restrict__ verts, float* __restrict__ out) {
    __shared__ int    s_j[8][MAXC];
    __shared__ double s_bsum;

    int tid = threadIdx.x;
    int lane = tid & 31;
    int wwid = tid >> 5;
    int row = (int)blockIdx.x * 8 + wwid;        // 1722*8 = 13776 exactly
    unsigned below = (1u << lane) - 1u;

    if (tid == 0) s_bsum = 0.0;

    // row AABB + ids (lane-uniform broadcast loads)
    float4 bmin = g_bb0[row];
    float4 bmax = g_bb1[row];
    int rp01 = __float_as_int(bmin.w);
    int rf0 = rp01 & 0xFFFF;
    int rf1 = rp01 >> 16;
    int rf2 = __float_as_int(bmax.w);

    // serial ballot scan, early exit; typical row: 1 chunk
    int found = 0;
    for (int base = 0; base < NUM_FACES && found < MAXC; base += 32) {
        int j = base + lane;
        bool ok = false;
        if (j < NUM_FACES) {                     // last chunk partial (16)
            float4 ja = g_bb0[j];
            float4 jb = g_bb1[j];
            ok = (bmin.x <= jb.x) && (ja.x <= bmax.x) &&
                 (bmin.y <= jb.y) && (ja.y <= bmax.y) &&
                 (bmin.z <= jb.z) && (ja.z <= bmax.z);
            if (ok) {
                int jp01 = __float_as_int(ja.w);
                int jf0 = jp01 & 0xFFFF;
                int jf1 = jp01 >> 16;
                int jf2 = __float_as_int(jb.w);
                bool share = (rf0 == jf0) | (rf0 == jf1) | (rf0 == jf2) |
                             (rf1 == jf0) | (rf1 == jf1) | (rf1 == jf2) |
                             (rf2 == jf0) | (rf2 == jf1) | (rf2 == jf2);
                ok = !share;
            }
        }
        unsigned m = __ballot_sync(0xffffffffu, ok);
        int rank = found + __popc(m & below);
        if (ok && rank < MAXC) s_j[wwid][rank] = j;
        found += __popc(m);
    }
    if (found > MAXC) found = MAXC;
    __syncwarp();

    // narrow phase: lanes 0..15 -> (pair 0..7) x (direction 0..1)
    float pen = 0.0f;
    int pairIdx = lane >> 1;
    if (lane < 16 && pairIdx < found) {
        int j = s_j[wwid][pairIdx];
        int jp01 = __float_as_int(g_bb0[j].w);   // L1-hot (touched in scan)
        int jf2  = __float_as_int(g_bb1[j].w);
        Tri R, J;
        R.v0 = vert3(verts, rf0);
        R.v1 = vert3(verts, rf1);
        R.v2 = vert3(verts, rf2);
        J.v0 = vert3(verts, jp01 & 0xFFFF);
        J.v1 = vert3(verts, jp01 >> 16);
        J.v2 = vert3(verts, jf2);
        pen = (lane & 1) ? cone_pen(J, R) : cone_pen(R, J);
    }
#pragma unroll
    for (int off = 16; off > 0; off >>= 1)
        pen += __shfl_xor_sync(0xffffffffu, pen, off);
    if (lane == 0 && pen != 0.0f) atomicAdd(&s_bsum, (double)pen);
    __syncthreads();

    // fused finalize: last-arriving block writes output + resets state
    if (tid == 0) {
        if (s_bsum != 0.0) atomicAdd(&g_accum, s_bsum);
        __threadfence();
        unsigned old = atomicAdd(&g_done, 1u);
        if (old == K2_BLOCKS - 1) {
            g_done = 0;                          // reset for graph replay
            unsigned long long bits =
                atomicExch((unsigned long long*)&g_accum, 0ULL);
            out[0] = (float)__longlong_as_double(bits);  // weight = 1.0
        }
    }
}

extern "C" void kernel_launch(void* const* d_in, const int* in_sizes, int n_in,
                              void* d_out, int out_size) {
    const float* verts = (const float*)d_in[0];
    const int*   faces = (const int*)d_in[1];
    float*       out   = (float*)d_out;

    setup_kernel<<<(NUM_FACES + 127) / 128, 128>>>(verts, faces);
    collide_kernel<<<K2_BLOCKS, 256>>>(verts, out);
}